// round 9
// baseline (speedup 1.0000x reference)
#include <cuda_runtime.h>
#include <cuda_fp16.h>
#include <cstdint>

// MeanConv: out = (1/7) * sum_{k in {3,5,7,9,11,13,15}} boxmean_k(x) * map
// Fused streaming kernel, packed f32x2 datapath, tuned for 5 blocks/SM:
//  - x rows staged via cp.async into an 8-row smem ring (wait+sync per 4 steps,
//    prefetch distance 4 rows)
//  - k=3,5: fp32x2 register rings (exact)
//  - k=7..15: fp16 smem rings, drift-accepting
//  - acc scatter via scalar FFMA with immediate weights (no weight registers)

namespace {

constexpr int IW = 4096;
constexpr int IH = 4096;
constexpr int TW = 256;      // columns per block
constexpr int NTH = 128;     // threads per block (2 columns each)
constexpr int SEGS = 46;
constexpr int SROWS = 90;    // 46*90 = 4140 >= 4096
constexpr int NSP = 5;       // smem planes: k = 7,9,11,13,15

__device__ constexpr int SDEP[NSP] = {8, 16, 16, 16, 16};
__device__ constexpr int SOFF[NSP] = {0, 8, 24, 40, 56};
constexpr int RINGROWS = 72;
constexpr int RING_BYTES = RINGROWS * NTH * 4;  // 36864

constexpr int XBUF_F = 272;  // 256 + 2*8 halo
constexpr int NXBUF = 8;
constexpr int XBUF_BYTES = NXBUF * XBUF_F * 4;       // 8704
constexpr int SMEM_BYTES = RING_BYTES + XBUF_BYTES;  // 45568 -> 5 blocks/SM

__device__ constexpr float WGT[7] = {
    1.0f / (7.0f * 9.0f),   1.0f / (7.0f * 25.0f),  1.0f / (7.0f * 49.0f),
    1.0f / (7.0f * 81.0f),  1.0f / (7.0f * 121.0f), 1.0f / (7.0f * 169.0f),
    1.0f / (7.0f * 225.0f)};

using u64 = unsigned long long;

__device__ __forceinline__ int clampi(int v, int lo, int hi) {
    return min(max(v, lo), hi);
}

// ---- packed f32x2 helpers ----
__device__ __forceinline__ u64 pk2(float lo, float hi) {
    u64 r;
    asm("mov.b64 %0, {%1, %2};" : "=l"(r) : "f"(lo), "f"(hi));
    return r;
}
__device__ __forceinline__ u64 bc2(float2 v) {
    u64 r;
    asm("mov.b64 %0, {%1, %2};" : "=l"(r) : "f"(v.x), "f"(v.y));
    return r;
}
__device__ __forceinline__ float2 un2(u64 v) {  // free: register-pair alias
    float2 f;
    asm("mov.b64 {%0, %1}, %2;" : "=f"(f.x), "=f"(f.y) : "l"(v));
    return f;
}
__device__ __forceinline__ u64 add2(u64 a, u64 b) {
    u64 r;
    asm("add.rn.f32x2 %0, %1, %2;" : "=l"(r) : "l"(a), "l"(b));
    return r;
}
__device__ __forceinline__ u64 sub2(u64 a, u64 b) {
    u64 r;
    asm("sub.rn.f32x2 %0, %1, %2;" : "=l"(r) : "l"(a), "l"(b));
    return r;
}
// pack f32x2 (as u64) -> f16x2 (rounded)
__device__ __forceinline__ unsigned int pk_h2(u64 v) {
    unsigned int h;
    asm("{\n\t.reg .f32 lo, hi;\n\tmov.b64 {lo, hi}, %1;\n\t"
        "cvt.rn.f16x2.f32 %0, hi, lo;\n\t}"
        : "=r"(h) : "l"(v));
    return h;
}
// unpack f16x2 -> f32x2 (as u64)
__device__ __forceinline__ u64 upk_h2(unsigned int h) {
    u64 r;
    asm("{\n\t.reg .f16 a, b;\n\t.reg .f32 lo, hi;\n\t"
        "mov.b32 {a, b}, %1;\n\tcvt.f32.f16 lo, a;\n\tcvt.f32.f16 hi, b;\n\t"
        "mov.b64 %0, {lo, hi};\n\t}"
        : "=l"(r) : "r"(h));
    return r;
}

// ---- cp.async ----
__device__ __forceinline__ void cp16(float* dst, const float* src) {
    unsigned int s = (unsigned int)__cvta_generic_to_shared(dst);
    asm volatile("cp.async.cg.shared.global [%0], [%1], 16;\n" ::"r"(s),
                 "l"(src));
}
__device__ __forceinline__ void cp4(float* dst, const float* src) {
    unsigned int s = (unsigned int)__cvta_generic_to_shared(dst);
    asm volatile("cp.async.ca.shared.global [%0], [%1], 4;\n" ::"r"(s),
                 "l"(src));
}
__device__ __forceinline__ void cp_commit() {
    asm volatile("cp.async.commit_group;\n");
}
template <int N>
__device__ __forceinline__ void cp_wait() {
    asm volatile("cp.async.wait_group %0;\n" ::"n"(N));
}

__device__ __forceinline__ void stage_row(float* __restrict__ dst,
                                          const float* __restrict__ x, int row,
                                          int cb, int tid, bool edge) {
    const float* rp = x + (size_t)clampi(row, 0, IH - 1) * IW;
    if (!edge) {
        if (tid < XBUF_F / 4) cp16(dst + 4 * tid, rp + cb - 8 + 4 * tid);
    } else {
#pragma unroll
        for (int rr = 0; rr < 3; ++rr) {
            int m = tid + rr * NTH;
            if (m < XBUF_F) cp4(dst + m, rp + clampi(cb - 8 + m, 0, IW - 1));
        }
    }
}

struct State {
    u64 rh3[4];
    u64 rh5[8];
    u64 T[7];
    float acc[8][2];
};

// One chunk of LEN steps starting at tb (tb - t0 is a multiple of 16, so all
// ring slots / acc indices are compile-time constants).
template <int LEN>
__device__ __forceinline__ void do_chunk(
    int tb, int r0, int r1, int cb, int c0,
    const float* __restrict__ x, const float* __restrict__ mp,
    float* __restrict__ outp, unsigned int* __restrict__ ring,
    float* __restrict__ xbuf, int tid, bool edge, State& st) {
#pragma unroll
    for (int p = 0; p < LEN; ++p) {
        const int t = tb + p;

        if ((p & 3) == 0) {
            cp_wait<0>();     // rows t..t+3 staged (issued 4 steps ago)
            __syncthreads();  // visible; slots (p+4..p+7)&7 fully consumed
#pragma unroll
            for (int i = 0; i < 4; ++i)
                stage_row(xbuf + ((p + 4 + i) & 7) * XBUF_F, x, t + 4 + i, cb,
                          tid, edge);
            cp_commit();
        }

        // Row t window: 9 aligned float2 loads (floats c0-8 .. c0+9).
        float2 xv[9];
        {
            const float2* xb2 = reinterpret_cast<const float2*>(
                xbuf + (p & 7) * XBUF_F + 2 * tid);
#pragma unroll
            for (int i = 0; i < 9; ++i) xv[i] = xb2[i];
        }

        // Horizontal box sums, packed per column pair.
        const u64 pc = bc2(xv[4]);
        const u64 pL1 = pk2(xv[3].y, xv[4].x);
        const u64 pR1 = pk2(xv[4].y, xv[5].x);
        const u64 pL3 = pk2(xv[2].y, xv[3].x);
        const u64 pR3 = pk2(xv[5].y, xv[6].x);
        const u64 pL5 = pk2(xv[1].y, xv[2].x);
        const u64 pR5 = pk2(xv[6].y, xv[7].x);
        const u64 pL7 = pk2(xv[0].y, xv[1].x);
        const u64 pR7 = pk2(xv[7].y, xv[8].x);

        u64 h[7];
        h[0] = add2(add2(pc, pL1), pR1);
        h[1] = add2(add2(h[0], bc2(xv[3])), bc2(xv[5]));
        h[2] = add2(add2(h[1], pL3), pR3);
        h[3] = add2(add2(h[2], bc2(xv[2])), bc2(xv[6]));
        h[4] = add2(add2(h[3], pL5), pR5);
        h[5] = add2(add2(h[4], bc2(xv[1])), bc2(xv[7]));
        h[6] = add2(add2(h[5], pL7), pR7);

        // k=3: fp32x2 register ring (exact).
        {
            const u64 old = st.rh3[(p + 1) & 3];  // (p-3)&3
            st.rh3[p & 3] = h[0];
            st.T[0] = add2(st.T[0], sub2(h[0], old));
            const float2 tf = un2(st.T[0]);
            const int a = (p - 1) & 7;
            st.acc[a][0] = fmaf(WGT[0], tf.x, st.acc[a][0]);
            st.acc[a][1] = fmaf(WGT[0], tf.y, st.acc[a][1]);
        }
        // k=5: fp32x2 register ring (exact).
        {
            const u64 old = st.rh5[(p + 3) & 7];  // (p-5)&7
            st.rh5[p & 7] = h[1];
            st.T[1] = add2(st.T[1], sub2(h[1], old));
            const float2 tf = un2(st.T[1]);
            const int a = (p - 2) & 7;
            st.acc[a][0] = fmaf(WGT[1], tf.x, st.acc[a][0]);
            st.acc[a][1] = fmaf(WGT[1], tf.y, st.acc[a][1]);
        }

        // k=7..15: fp16 smem rings, drift-accepting.
#pragma unroll
        for (int j = 0; j < NSP; ++j) {
            const int r = j + 2;
            const int k = 2 * r + 3;
            const int d = SDEP[j];
            const int sw = p & (d - 1);
            const int sr = (p - k + 16) & (d - 1);

            const unsigned int oldh = ring[(SOFF[j] + sr) * NTH + tid];
            ring[(SOFF[j] + sw) * NTH + tid] = pk_h2(h[r]);

            st.T[r] = add2(st.T[r], sub2(h[r], upk_h2(oldh)));
            const float2 tf = un2(st.T[r]);
            const int a = (p - (r + 1)) & 7;
            st.acc[a][0] = fmaf(WGT[r], tf.x, st.acc[a][0]);
            st.acc[a][1] = fmaf(WGT[r], tf.y, st.acc[a][1]);
        }

        // Row t-7 complete: load map, multiply, store, reset slot.
        const int orow = t - 7;
        const int fa = (p + 1) & 7;  // == (p - 7) & 7
        if (orow >= r0 && orow < r1) {
            const float2 mv = *reinterpret_cast<const float2*>(
                mp + (size_t)orow * IW + c0);
            float2 ov;
            ov.x = st.acc[fa][0] * mv.x;
            ov.y = st.acc[fa][1] * mv.y;
            *reinterpret_cast<float2*>(outp + (size_t)orow * IW + c0) = ov;
        }
        st.acc[fa][0] = 0.0f;
        st.acc[fa][1] = 0.0f;
    }
}

}  // namespace

__global__ void __launch_bounds__(NTH, 5)
MeanConv_82008105549850_kernel(const float* __restrict__ x,
                               const float* __restrict__ mp,
                               float* __restrict__ outp) {
    extern __shared__ __align__(16) char smem_raw[];
    unsigned int* ring = reinterpret_cast<unsigned int*>(smem_raw);  // f16x2
    float* xbuf = reinterpret_cast<float*>(smem_raw + RING_BYTES);

    const int tid = threadIdx.x;
    const int cb = blockIdx.x * TW;
    const bool edge = (cb == 0) || (cb + TW == IW);
    const int r0 = blockIdx.y * SROWS;
    const int r1 = min(r0 + SROWS, IH);
    const int c0 = cb + 2 * tid;

    const int t0 = r0 - 7;  // 7 warm-up rows; 104 steps = 6*16 + 8

    // Kick off the first staging group ASAP (overlaps ring zero-init).
#pragma unroll
    for (int i = 0; i < 4; ++i)
        stage_row(xbuf + i * XBUF_F, x, t0 + i, cb, tid, edge);
    cp_commit();

    // Zero this thread's ring column (open-window warm-up). Private -> no sync.
#pragma unroll
    for (int s = 0; s < RINGROWS; ++s) ring[s * NTH + tid] = 0u;

    State st;
#pragma unroll
    for (int i = 0; i < 4; ++i) st.rh3[i] = 0ull;
#pragma unroll
    for (int i = 0; i < 8; ++i) st.rh5[i] = 0ull;
#pragma unroll
    for (int r = 0; r < 7; ++r) st.T[r] = 0ull;
#pragma unroll
    for (int a = 0; a < 8; ++a) st.acc[a][0] = st.acc[a][1] = 0.0f;

    for (int chunk = 0; chunk < 6; ++chunk) {
        do_chunk<16>(t0 + chunk * 16, r0, r1, cb, c0, x, mp, outp, ring, xbuf,
                     tid, edge, st);
    }
    do_chunk<8>(t0 + 96, r0, r1, cb, c0, x, mp, outp, ring, xbuf, tid, edge,
                st);
}

extern "C" void kernel_launch(void* const* d_in, const int* in_sizes, int n_in,
                              void* d_out, int out_size) {
    const float* x = (const float*)d_in[0];
    const float* mp = (const float*)d_in[1];
    float* outp = (float*)d_out;

    cudaFuncSetAttribute(MeanConv_82008105549850_kernel,
                         cudaFuncAttributeMaxDynamicSharedMemorySize,
                         SMEM_BYTES);

    dim3 grid(IW / TW, SEGS);  // 16 x 46 = 736 blocks ~= one wave at 5/SM
    MeanConv_82008105549850_kernel<<<grid, NTH, SMEM_BYTES>>>(x, mp, outp);
}

// round 11
// speedup vs baseline: 1.1546x; 1.1546x over previous
#include <cuda_runtime.h>
#include <cuda_fp16.h>
#include <cstdint>

// MeanConv: out = (1/7) * sum_{k in {3,5,7,9,11,13,15}} boxmean_k(x) * map
// Fused streaming kernel, packed f32x2 datapath. R8 pipeline (16-slot x ring,
// wait<2>, 12-row prefetch distance) + register rings for k=3,5,7 + 4-step
// register map prefetch. k=9..15 in fp16 smem rings (drift-accepting).

namespace {

constexpr int IW = 4096;
constexpr int IH = 4096;
constexpr int TW = 256;      // columns per block
constexpr int NTH = 128;     // threads per block (2 columns each)
constexpr int SEGS = 36;
constexpr int SROWS = 114;   // 36*114 = 4104 >= 4096
constexpr int NSP = 4;       // smem planes: k = 9,11,13,15

__device__ constexpr int SOFF[NSP] = {0, 16, 32, 48};  // all depth 16
constexpr int RINGROWS = 64;
constexpr int RING_BYTES = RINGROWS * NTH * 4;  // 32768

constexpr int XBUF_F = 272;  // 256 + 2*8 halo
constexpr int NXBUF = 16;
constexpr int XBUF_BYTES = NXBUF * XBUF_F * 4;       // 17408
constexpr int SMEM_BYTES = RING_BYTES + XBUF_BYTES;  // 50176 -> 4 blocks/SM

__device__ constexpr float WGT[7] = {
    1.0f / (7.0f * 9.0f),   1.0f / (7.0f * 25.0f),  1.0f / (7.0f * 49.0f),
    1.0f / (7.0f * 81.0f),  1.0f / (7.0f * 121.0f), 1.0f / (7.0f * 169.0f),
    1.0f / (7.0f * 225.0f)};

using u64 = unsigned long long;

__device__ __forceinline__ int clampi(int v, int lo, int hi) {
    return min(max(v, lo), hi);
}

// ---- packed f32x2 helpers ----
__device__ __forceinline__ u64 pk2(float lo, float hi) {
    u64 r;
    asm("mov.b64 %0, {%1, %2};" : "=l"(r) : "f"(lo), "f"(hi));
    return r;
}
__device__ __forceinline__ u64 bc2(float2 v) {
    u64 r;
    asm("mov.b64 %0, {%1, %2};" : "=l"(r) : "f"(v.x), "f"(v.y));
    return r;
}
__device__ __forceinline__ float2 un2(u64 v) {  // register-pair alias
    float2 f;
    asm("mov.b64 {%0, %1}, %2;" : "=f"(f.x), "=f"(f.y) : "l"(v));
    return f;
}
__device__ __forceinline__ u64 add2(u64 a, u64 b) {
    u64 r;
    asm("add.rn.f32x2 %0, %1, %2;" : "=l"(r) : "l"(a), "l"(b));
    return r;
}
__device__ __forceinline__ u64 sub2(u64 a, u64 b) {
    u64 r;
    asm("sub.rn.f32x2 %0, %1, %2;" : "=l"(r) : "l"(a), "l"(b));
    return r;
}
// pack f32x2 (as u64) -> f16x2 (rounded)
__device__ __forceinline__ unsigned int pk_h2(u64 v) {
    unsigned int h;
    asm("{\n\t.reg .f32 lo, hi;\n\tmov.b64 {lo, hi}, %1;\n\t"
        "cvt.rn.f16x2.f32 %0, hi, lo;\n\t}"
        : "=r"(h) : "l"(v));
    return h;
}
// unpack f16x2 -> f32x2 (as u64)
__device__ __forceinline__ u64 upk_h2(unsigned int h) {
    u64 r;
    asm("{\n\t.reg .f16 a, b;\n\t.reg .f32 lo, hi;\n\t"
        "mov.b32 {a, b}, %1;\n\tcvt.f32.f16 lo, a;\n\tcvt.f32.f16 hi, b;\n\t"
        "mov.b64 %0, {lo, hi};\n\t}"
        : "=l"(r) : "r"(h));
    return r;
}

// ---- cp.async ----
__device__ __forceinline__ void cp16(float* dst, const float* src) {
    unsigned int s = (unsigned int)__cvta_generic_to_shared(dst);
    asm volatile("cp.async.cg.shared.global [%0], [%1], 16;\n" ::"r"(s),
                 "l"(src));
}
__device__ __forceinline__ void cp4(float* dst, const float* src) {
    unsigned int s = (unsigned int)__cvta_generic_to_shared(dst);
    asm volatile("cp.async.ca.shared.global [%0], [%1], 4;\n" ::"r"(s),
                 "l"(src));
}
__device__ __forceinline__ void cp_commit() {
    asm volatile("cp.async.commit_group;\n");
}
template <int N>
__device__ __forceinline__ void cp_wait() {
    asm volatile("cp.async.wait_group %0;\n" ::"n"(N));
}

__device__ __forceinline__ void stage_row(float* __restrict__ dst,
                                          const float* __restrict__ x, int row,
                                          int cb, int tid, bool edge) {
    const float* rp = x + (size_t)clampi(row, 0, IH - 1) * IW;
    if (!edge) {
        if (tid < XBUF_F / 4) cp16(dst + 4 * tid, rp + cb - 8 + 4 * tid);
    } else {
#pragma unroll
        for (int rr = 0; rr < 3; ++rr) {
            int m = tid + rr * NTH;
            if (m < XBUF_F) cp4(dst + m, rp + clampi(cb - 8 + m, 0, IW - 1));
        }
    }
}

struct State {
    u64 rh3[4];
    u64 rh5[8];
    u64 rh7[8];
    u64 T[7];
    u64 mpipe[4];  // map rows, 4-step prefetch distance
    float acc[8][2];
};

// One 16-step chunk; tb - t0 is a multiple of 16, so all ring slots and acc
// indices are compile-time constants.
__device__ __forceinline__ void do_chunk(
    int tb, int r0, int r1, int cb, int c0,
    const float* __restrict__ x, const float* __restrict__ mp,
    float* __restrict__ outp, unsigned int* __restrict__ ring,
    float* __restrict__ xbuf, int tid, bool edge, State& st) {
#pragma unroll
    for (int p = 0; p < 16; ++p) {
        const int t = tb + p;

        if ((p & 3) == 0) {
            cp_wait<2>();     // rows t..t+3 staged (distance 12)
            __syncthreads();  // visible; slots (p+12..15)&15 consumed
#pragma unroll
            for (int i = 0; i < 4; ++i)
                stage_row(xbuf + ((p + 12 + i) & 15) * XBUF_F, x, t + 12 + i,
                          cb, tid, edge);
            cp_commit();
        }

        // Map pipeline: take this step's value (row t-7, loaded 4 steps ago),
        // then issue the load for row t-3 into the same slot.
        const int ms = (p + 1) & 3;  // (t-7)&3 == (t-3)&3
        const u64 mv = st.mpipe[ms];
        {
            const int lr = t - 3;
            u64 nm = 0ull;
            if (lr >= r0 && lr < r1)
                nm = *reinterpret_cast<const u64*>(mp + (size_t)lr * IW + c0);
            st.mpipe[ms] = nm;
        }

        // Row t window: 9 aligned float2 loads (floats c0-8 .. c0+9).
        float2 xv[9];
        {
            const float2* xb2 =
                reinterpret_cast<const float2*>(xbuf + p * XBUF_F + 2 * tid);
#pragma unroll
            for (int i = 0; i < 9; ++i) xv[i] = xb2[i];
        }

        // Horizontal box sums, packed per column pair.
        const u64 pc = bc2(xv[4]);
        const u64 pL1 = pk2(xv[3].y, xv[4].x);
        const u64 pR1 = pk2(xv[4].y, xv[5].x);
        const u64 pL3 = pk2(xv[2].y, xv[3].x);
        const u64 pR3 = pk2(xv[5].y, xv[6].x);
        const u64 pL5 = pk2(xv[1].y, xv[2].x);
        const u64 pR5 = pk2(xv[6].y, xv[7].x);
        const u64 pL7 = pk2(xv[0].y, xv[1].x);
        const u64 pR7 = pk2(xv[7].y, xv[8].x);

        u64 h[7];
        h[0] = add2(add2(pc, pL1), pR1);
        h[1] = add2(add2(h[0], bc2(xv[3])), bc2(xv[5]));
        h[2] = add2(add2(h[1], pL3), pR3);
        h[3] = add2(add2(h[2], bc2(xv[2])), bc2(xv[6]));
        h[4] = add2(add2(h[3], pL5), pR5);
        h[5] = add2(add2(h[4], bc2(xv[1])), bc2(xv[7]));
        h[6] = add2(add2(h[5], pL7), pR7);

        // k=3: fp32x2 register ring (exact).
        {
            const u64 old = st.rh3[(p + 1) & 3];  // (p-3)&3
            st.rh3[p & 3] = h[0];
            st.T[0] = add2(st.T[0], sub2(h[0], old));
            const float2 tf = un2(st.T[0]);
            const int a = (p - 1) & 7;
            st.acc[a][0] = fmaf(WGT[0], tf.x, st.acc[a][0]);
            st.acc[a][1] = fmaf(WGT[0], tf.y, st.acc[a][1]);
        }
        // k=5: fp32x2 register ring (exact).
        {
            const u64 old = st.rh5[(p + 3) & 7];  // (p-5)&7
            st.rh5[p & 7] = h[1];
            st.T[1] = add2(st.T[1], sub2(h[1], old));
            const float2 tf = un2(st.T[1]);
            const int a = (p - 2) & 7;
            st.acc[a][0] = fmaf(WGT[1], tf.x, st.acc[a][0]);
            st.acc[a][1] = fmaf(WGT[1], tf.y, st.acc[a][1]);
        }
        // k=7: fp32x2 register ring (exact).
        {
            const u64 old = st.rh7[(p + 1) & 7];  // (p-7)&7
            st.rh7[p & 7] = h[2];
            st.T[2] = add2(st.T[2], sub2(h[2], old));
            const float2 tf = un2(st.T[2]);
            const int a = (p - 3) & 7;
            st.acc[a][0] = fmaf(WGT[2], tf.x, st.acc[a][0]);
            st.acc[a][1] = fmaf(WGT[2], tf.y, st.acc[a][1]);
        }

        // k=9..15: fp16 smem rings (depth 16), drift-accepting.
#pragma unroll
        for (int j = 0; j < NSP; ++j) {
            const int r = j + 3;
            const int k = 2 * r + 3;
            const int sw = p & 15;
            const int sr = (p - k + 16) & 15;

            const unsigned int oldh = ring[(SOFF[j] + sr) * NTH + tid];
            ring[(SOFF[j] + sw) * NTH + tid] = pk_h2(h[r]);

            st.T[r] = add2(st.T[r], sub2(h[r], upk_h2(oldh)));
            const float2 tf = un2(st.T[r]);
            const int a = (p - (r + 1)) & 7;
            st.acc[a][0] = fmaf(WGT[r], tf.x, st.acc[a][0]);
            st.acc[a][1] = fmaf(WGT[r], tf.y, st.acc[a][1]);
        }

        // Row t-7 complete: multiply by map (prefetched 4 steps ago), store.
        const int orow = t - 7;
        const int fa = (p + 1) & 7;  // == (p - 7) & 7
        if (orow >= r0 && orow < r1) {
            const float2 mf = un2(mv);
            float2 ov;
            ov.x = st.acc[fa][0] * mf.x;
            ov.y = st.acc[fa][1] * mf.y;
            *reinterpret_cast<float2*>(outp + (size_t)orow * IW + c0) = ov;
        }
        st.acc[fa][0] = 0.0f;
        st.acc[fa][1] = 0.0f;
    }
}

}  // namespace

__global__ void __launch_bounds__(NTH, 4)
MeanConv_82008105549850_kernel(const float* __restrict__ x,
                               const float* __restrict__ mp,
                               float* __restrict__ outp) {
    extern __shared__ __align__(16) char smem_raw[];
    unsigned int* ring = reinterpret_cast<unsigned int*>(smem_raw);  // f16x2
    float* xbuf = reinterpret_cast<float*>(smem_raw + RING_BYTES);

    const int tid = threadIdx.x;
    const int cb = blockIdx.x * TW;
    const bool edge = (cb == 0) || (cb + TW == IW);
    const int r0 = blockIdx.y * SROWS;
    const int r1 = min(r0 + SROWS, IH);
    const int c0 = cb + 2 * tid;

    const int t0 = r0 - 7;  // 7 warm-up rows; 128 steps = 8 chunks of 16

    // Prologue: stage rows t0..t0+11 as 3 groups of 4 into slots 0..11.
#pragma unroll
    for (int g = 0; g < 3; ++g) {
#pragma unroll
        for (int i = 0; i < 4; ++i)
            stage_row(xbuf + (4 * g + i) * XBUF_F, x, t0 + 4 * g + i, cb, tid,
                      edge);
        cp_commit();
    }

    // Zero this thread's ring column (open-window warm-up). Private -> no sync.
#pragma unroll
    for (int s = 0; s < RINGROWS; ++s) ring[s * NTH + tid] = 0u;

    State st;
#pragma unroll
    for (int i = 0; i < 4; ++i) st.rh3[i] = 0ull;
#pragma unroll
    for (int i = 0; i < 8; ++i) st.rh5[i] = 0ull;
#pragma unroll
    for (int i = 0; i < 8; ++i) st.rh7[i] = 0ull;
#pragma unroll
    for (int r = 0; r < 7; ++r) st.T[r] = 0ull;
#pragma unroll
    for (int i = 0; i < 4; ++i) st.mpipe[i] = 0ull;
#pragma unroll
    for (int a = 0; a < 8; ++a) st.acc[a][0] = st.acc[a][1] = 0.0f;

    for (int chunk = 0; chunk < 8; ++chunk) {
        do_chunk(t0 + chunk * 16, r0, r1, cb, c0, x, mp, outp, ring, xbuf, tid,
                 edge, st);
    }
}

extern "C" void kernel_launch(void* const* d_in, const int* in_sizes, int n_in,
                              void* d_out, int out_size) {
    const float* x = (const float*)d_in[0];
    const float* mp = (const float*)d_in[1];
    float* outp = (float*)d_out;

    cudaFuncSetAttribute(MeanConv_82008105549850_kernel,
                         cudaFuncAttributeMaxDynamicSharedMemorySize,
                         SMEM_BYTES);

    dim3 grid(IW / TW, SEGS);  // 16 x 36 = 576 blocks, 4/SM
    MeanConv_82008105549850_kernel<<<grid, NTH, SMEM_BYTES>>>(x, mp, outp);
}

// round 12
// speedup vs baseline: 1.1802x; 1.0222x over previous
#include <cuda_runtime.h>
#include <cuda_fp16.h>
#include <cstdint>

// MeanConv: out = (1/7) * sum_{k in {3,5,7,9,11,13,15}} boxmean_k(x) * map
// Fused streaming kernel, packed f32x2 datapath. R8 pipeline (16-slot x ring,
// wait<2>, 12-row prefetch distance) + register rings for k=3,5,7 + 4-step
// register map prefetch. k=9..15 in fp16 smem rings (drift-accepting).

namespace {

constexpr int IW = 4096;
constexpr int IH = 4096;
constexpr int TW = 256;      // columns per block
constexpr int NTH = 128;     // threads per block (2 columns each)
constexpr int SEGS = 36;
constexpr int SROWS = 114;   // 36*114 = 4104 >= 4096
constexpr int NSP = 4;       // smem planes: k = 9,11,13,15

__device__ constexpr int SOFF[NSP] = {0, 16, 32, 48};  // all depth 16
constexpr int RINGROWS = 64;
constexpr int RING_BYTES = RINGROWS * NTH * 4;  // 32768

constexpr int XBUF_F = 272;  // 256 + 2*8 halo
constexpr int NXBUF = 16;
constexpr int XBUF_BYTES = NXBUF * XBUF_F * 4;       // 17408
constexpr int SMEM_BYTES = RING_BYTES + XBUF_BYTES;  // 50176 -> 4 blocks/SM

__device__ constexpr float WGT[7] = {
    1.0f / (7.0f * 9.0f),   1.0f / (7.0f * 25.0f),  1.0f / (7.0f * 49.0f),
    1.0f / (7.0f * 81.0f),  1.0f / (7.0f * 121.0f), 1.0f / (7.0f * 169.0f),
    1.0f / (7.0f * 225.0f)};

using u64 = unsigned long long;

__device__ __forceinline__ int clampi(int v, int lo, int hi) {
    return min(max(v, lo), hi);
}

// ---- packed f32x2 helpers ----
__device__ __forceinline__ u64 pk2(float lo, float hi) {
    u64 r;
    asm("mov.b64 %0, {%1, %2};" : "=l"(r) : "f"(lo), "f"(hi));
    return r;
}
__device__ __forceinline__ u64 bc2(float2 v) {
    u64 r;
    asm("mov.b64 %0, {%1, %2};" : "=l"(r) : "f"(v.x), "f"(v.y));
    return r;
}
__device__ __forceinline__ float2 un2(u64 v) {  // register-pair alias
    float2 f;
    asm("mov.b64 {%0, %1}, %2;" : "=f"(f.x), "=f"(f.y) : "l"(v));
    return f;
}
__device__ __forceinline__ u64 add2(u64 a, u64 b) {
    u64 r;
    asm("add.rn.f32x2 %0, %1, %2;" : "=l"(r) : "l"(a), "l"(b));
    return r;
}
__device__ __forceinline__ u64 sub2(u64 a, u64 b) {
    u64 r;
    asm("sub.rn.f32x2 %0, %1, %2;" : "=l"(r) : "l"(a), "l"(b));
    return r;
}
// pack f32x2 (as u64) -> f16x2 (rounded)
__device__ __forceinline__ unsigned int pk_h2(u64 v) {
    unsigned int h;
    asm("{\n\t.reg .f32 lo, hi;\n\tmov.b64 {lo, hi}, %1;\n\t"
        "cvt.rn.f16x2.f32 %0, hi, lo;\n\t}"
        : "=r"(h) : "l"(v));
    return h;
}
// unpack f16x2 -> f32x2 (as u64)
__device__ __forceinline__ u64 upk_h2(unsigned int h) {
    u64 r;
    asm("{\n\t.reg .f16 a, b;\n\t.reg .f32 lo, hi;\n\t"
        "mov.b32 {a, b}, %1;\n\tcvt.f32.f16 lo, a;\n\tcvt.f32.f16 hi, b;\n\t"
        "mov.b64 %0, {lo, hi};\n\t}"
        : "=l"(r) : "r"(h));
    return r;
}

// ---- cp.async ----
__device__ __forceinline__ void cp16(float* dst, const float* src) {
    unsigned int s = (unsigned int)__cvta_generic_to_shared(dst);
    asm volatile("cp.async.cg.shared.global [%0], [%1], 16;\n" ::"r"(s),
                 "l"(src));
}
__device__ __forceinline__ void cp4(float* dst, const float* src) {
    unsigned int s = (unsigned int)__cvta_generic_to_shared(dst);
    asm volatile("cp.async.ca.shared.global [%0], [%1], 4;\n" ::"r"(s),
                 "l"(src));
}
__device__ __forceinline__ void cp_commit() {
    asm volatile("cp.async.commit_group;\n");
}
template <int N>
__device__ __forceinline__ void cp_wait() {
    asm volatile("cp.async.wait_group %0;\n" ::"n"(N));
}

__device__ __forceinline__ void stage_row(float* __restrict__ dst,
                                          const float* __restrict__ x, int row,
                                          int cb, int tid, bool edge) {
    const float* rp = x + (size_t)clampi(row, 0, IH - 1) * IW;
    if (!edge) {
        if (tid < XBUF_F / 4) cp16(dst + 4 * tid, rp + cb - 8 + 4 * tid);
    } else {
#pragma unroll
        for (int rr = 0; rr < 3; ++rr) {
            int m = tid + rr * NTH;
            if (m < XBUF_F) cp4(dst + m, rp + clampi(cb - 8 + m, 0, IW - 1));
        }
    }
}

struct State {
    u64 rh3[4];
    u64 rh5[8];
    u64 rh7[8];
    u64 T[7];
    u64 mpipe[4];  // map rows, 4-step prefetch distance
    float acc[8][2];
};

// One 16-step chunk; tb - t0 is a multiple of 16, so all ring slots and acc
// indices are compile-time constants.
__device__ __forceinline__ void do_chunk(
    int tb, int r0, int r1, int cb, int c0,
    const float* __restrict__ x, const float* __restrict__ mp,
    float* __restrict__ outp, unsigned int* __restrict__ ring,
    float* __restrict__ xbuf, int tid, bool edge, State& st) {
#pragma unroll
    for (int p = 0; p < 16; ++p) {
        const int t = tb + p;

        if ((p & 3) == 0) {
            cp_wait<2>();     // rows t..t+3 staged (distance 12)
            __syncthreads();  // visible; slots (p+12..15)&15 consumed
#pragma unroll
            for (int i = 0; i < 4; ++i)
                stage_row(xbuf + ((p + 12 + i) & 15) * XBUF_F, x, t + 12 + i,
                          cb, tid, edge);
            cp_commit();
        }

        // Map pipeline: take this step's value (row t-7, loaded 4 steps ago),
        // then issue the load for row t-3 into the same slot.
        const int ms = (p + 1) & 3;  // (t-7)&3 == (t-3)&3
        const u64 mv = st.mpipe[ms];
        {
            const int lr = t - 3;
            u64 nm = 0ull;
            if (lr >= r0 && lr < r1)
                nm = *reinterpret_cast<const u64*>(mp + (size_t)lr * IW + c0);
            st.mpipe[ms] = nm;
        }

        // Row t window: 9 aligned float2 loads (floats c0-8 .. c0+9).
        float2 xv[9];
        {
            const float2* xb2 =
                reinterpret_cast<const float2*>(xbuf + p * XBUF_F + 2 * tid);
#pragma unroll
            for (int i = 0; i < 9; ++i) xv[i] = xb2[i];
        }

        // Horizontal box sums, packed per column pair.
        const u64 pc = bc2(xv[4]);
        const u64 pL1 = pk2(xv[3].y, xv[4].x);
        const u64 pR1 = pk2(xv[4].y, xv[5].x);
        const u64 pL3 = pk2(xv[2].y, xv[3].x);
        const u64 pR3 = pk2(xv[5].y, xv[6].x);
        const u64 pL5 = pk2(xv[1].y, xv[2].x);
        const u64 pR5 = pk2(xv[6].y, xv[7].x);
        const u64 pL7 = pk2(xv[0].y, xv[1].x);
        const u64 pR7 = pk2(xv[7].y, xv[8].x);

        u64 h[7];
        h[0] = add2(add2(pc, pL1), pR1);
        h[1] = add2(add2(h[0], bc2(xv[3])), bc2(xv[5]));
        h[2] = add2(add2(h[1], pL3), pR3);
        h[3] = add2(add2(h[2], bc2(xv[2])), bc2(xv[6]));
        h[4] = add2(add2(h[3], pL5), pR5);
        h[5] = add2(add2(h[4], bc2(xv[1])), bc2(xv[7]));
        h[6] = add2(add2(h[5], pL7), pR7);

        // k=3: fp32x2 register ring (exact).
        {
            const u64 old = st.rh3[(p + 1) & 3];  // (p-3)&3
            st.rh3[p & 3] = h[0];
            st.T[0] = add2(st.T[0], sub2(h[0], old));
            const float2 tf = un2(st.T[0]);
            const int a = (p - 1) & 7;
            st.acc[a][0] = fmaf(WGT[0], tf.x, st.acc[a][0]);
            st.acc[a][1] = fmaf(WGT[0], tf.y, st.acc[a][1]);
        }
        // k=5: fp32x2 register ring (exact).
        {
            const u64 old = st.rh5[(p + 3) & 7];  // (p-5)&7
            st.rh5[p & 7] = h[1];
            st.T[1] = add2(st.T[1], sub2(h[1], old));
            const float2 tf = un2(st.T[1]);
            const int a = (p - 2) & 7;
            st.acc[a][0] = fmaf(WGT[1], tf.x, st.acc[a][0]);
            st.acc[a][1] = fmaf(WGT[1], tf.y, st.acc[a][1]);
        }
        // k=7: fp32x2 register ring (exact).
        {
            const u64 old = st.rh7[(p + 1) & 7];  // (p-7)&7
            st.rh7[p & 7] = h[2];
            st.T[2] = add2(st.T[2], sub2(h[2], old));
            const float2 tf = un2(st.T[2]);
            const int a = (p - 3) & 7;
            st.acc[a][0] = fmaf(WGT[2], tf.x, st.acc[a][0]);
            st.acc[a][1] = fmaf(WGT[2], tf.y, st.acc[a][1]);
        }

        // k=9..15: fp16 smem rings (depth 16), drift-accepting.
#pragma unroll
        for (int j = 0; j < NSP; ++j) {
            const int r = j + 3;
            const int k = 2 * r + 3;
            const int sw = p & 15;
            const int sr = (p - k + 16) & 15;

            const unsigned int oldh = ring[(SOFF[j] + sr) * NTH + tid];
            ring[(SOFF[j] + sw) * NTH + tid] = pk_h2(h[r]);

            st.T[r] = add2(st.T[r], sub2(h[r], upk_h2(oldh)));
            const float2 tf = un2(st.T[r]);
            const int a = (p - (r + 1)) & 7;
            st.acc[a][0] = fmaf(WGT[r], tf.x, st.acc[a][0]);
            st.acc[a][1] = fmaf(WGT[r], tf.y, st.acc[a][1]);
        }

        // Row t-7 complete: multiply by map (prefetched 4 steps ago), store.
        const int orow = t - 7;
        const int fa = (p + 1) & 7;  // == (p - 7) & 7
        if (orow >= r0 && orow < r1) {
            const float2 mf = un2(mv);
            float2 ov;
            ov.x = st.acc[fa][0] * mf.x;
            ov.y = st.acc[fa][1] * mf.y;
            *reinterpret_cast<float2*>(outp + (size_t)orow * IW + c0) = ov;
        }
        st.acc[fa][0] = 0.0f;
        st.acc[fa][1] = 0.0f;
    }
}

}  // namespace

__global__ void __launch_bounds__(NTH, 4)
MeanConv_82008105549850_kernel(const float* __restrict__ x,
                               const float* __restrict__ mp,
                               float* __restrict__ outp) {
    extern __shared__ __align__(16) char smem_raw[];
    unsigned int* ring = reinterpret_cast<unsigned int*>(smem_raw);  // f16x2
    float* xbuf = reinterpret_cast<float*>(smem_raw + RING_BYTES);

    const int tid = threadIdx.x;
    const int cb = blockIdx.x * TW;
    const bool edge = (cb == 0) || (cb + TW == IW);
    const int r0 = blockIdx.y * SROWS;
    const int r1 = min(r0 + SROWS, IH);
    const int c0 = cb + 2 * tid;

    const int t0 = r0 - 7;  // 7 warm-up rows; 128 steps = 8 chunks of 16

    // Prologue: stage rows t0..t0+11 as 3 groups of 4 into slots 0..11.
#pragma unroll
    for (int g = 0; g < 3; ++g) {
#pragma unroll
        for (int i = 0; i < 4; ++i)
            stage_row(xbuf + (4 * g + i) * XBUF_F, x, t0 + 4 * g + i, cb, tid,
                      edge);
        cp_commit();
    }

    // Zero this thread's ring column (open-window warm-up). Private -> no sync.
#pragma unroll
    for (int s = 0; s < RINGROWS; ++s) ring[s * NTH + tid] = 0u;

    State st;
#pragma unroll
    for (int i = 0; i < 4; ++i) st.rh3[i] = 0ull;
#pragma unroll
    for (int i = 0; i < 8; ++i) st.rh5[i] = 0ull;
#pragma unroll
    for (int i = 0; i < 8; ++i) st.rh7[i] = 0ull;
#pragma unroll
    for (int r = 0; r < 7; ++r) st.T[r] = 0ull;
#pragma unroll
    for (int i = 0; i < 4; ++i) st.mpipe[i] = 0ull;
#pragma unroll
    for (int a = 0; a < 8; ++a) st.acc[a][0] = st.acc[a][1] = 0.0f;

    for (int chunk = 0; chunk < 8; ++chunk) {
        do_chunk(t0 + chunk * 16, r0, r1, cb, c0, x, mp, outp, ring, xbuf, tid,
                 edge, st);
    }
}

extern "C" void kernel_launch(void* const* d_in, const int* in_sizes, int n_in,
                              void* d_out, int out_size) {
    const float* x = (const float*)d_in[0];
    const float* mp = (const float*)d_in[1];
    float* outp = (float*)d_out;

    cudaFuncSetAttribute(MeanConv_82008105549850_kernel,
                         cudaFuncAttributeMaxDynamicSharedMemorySize,
                         SMEM_BYTES);

    dim3 grid(IW / TW, SEGS);  // 16 x 36 = 576 blocks, 4/SM
    MeanConv_82008105549850_kernel<<<grid, NTH, SMEM_BYTES>>>(x, mp, outp);
}

// round 15
// speedup vs baseline: 1.2904x; 1.0934x over previous
#include <cuda_runtime.h>
#include <cuda_fp16.h>
#include <cstdint>

// MeanConv: out = (1/7) * sum_{k in {3,5,7,9,11,13,15}} boxmean_k(x) * map
// Fused streaming kernel with packed f32x2 datapath (R8 structure):
//  - x rows staged via cp.async into a 16-row smem ring (wait<2>, distance 12)
//  - k=3,5: fp32x2 register rings (exact)
//  - k=7..15: fp16 smem rings, drift-accepting
//  - acc scatter via scalar FFMA with immediate weights (no weight registers)
//  - SEGS=37 -> 125 steps/block, grid 592 = exactly one wave at 4/SM

namespace {

constexpr int IW = 4096;
constexpr int IH = 4096;
constexpr int TW = 256;      // columns per block
constexpr int NTH = 128;     // threads per block (2 columns each)
constexpr int SEGS = 37;
constexpr int SROWS = 111;   // 37*111 = 4107 >= 4096
constexpr int NSP = 5;       // smem planes: k = 7,9,11,13,15

__device__ constexpr int SDEP[NSP] = {8, 16, 16, 16, 16};
__device__ constexpr int SOFF[NSP] = {0, 8, 24, 40, 56};
constexpr int RINGROWS = 72;
constexpr int RING_BYTES = RINGROWS * NTH * 4;  // 36864

constexpr int XBUF_F = 272;  // 256 + 2*8 halo
constexpr int NXBUF = 16;
constexpr int XBUF_BYTES = NXBUF * XBUF_F * 4;       // 17408
constexpr int SMEM_BYTES = RING_BYTES + XBUF_BYTES;  // 54272 -> 4 blocks/SM

__device__ constexpr float WGT[7] = {
    1.0f / (7.0f * 9.0f),   1.0f / (7.0f * 25.0f),  1.0f / (7.0f * 49.0f),
    1.0f / (7.0f * 81.0f),  1.0f / (7.0f * 121.0f), 1.0f / (7.0f * 169.0f),
    1.0f / (7.0f * 225.0f)};

using u64 = unsigned long long;

__device__ __forceinline__ int clampi(int v, int lo, int hi) {
    return min(max(v, lo), hi);
}

// ---- packed f32x2 helpers ----
__device__ __forceinline__ u64 pk2(float lo, float hi) {
    u64 r;
    asm("mov.b64 %0, {%1, %2};" : "=l"(r) : "f"(lo), "f"(hi));
    return r;
}
__device__ __forceinline__ u64 bc2(float2 v) {
    u64 r;
    asm("mov.b64 %0, {%1, %2};" : "=l"(r) : "f"(v.x), "f"(v.y));
    return r;
}
__device__ __forceinline__ float2 un2(u64 v) {  // register-pair alias
    float2 f;
    asm("mov.b64 {%0, %1}, %2;" : "=f"(f.x), "=f"(f.y) : "l"(v));
    return f;
}
__device__ __forceinline__ u64 add2(u64 a, u64 b) {
    u64 r;
    asm("add.rn.f32x2 %0, %1, %2;" : "=l"(r) : "l"(a), "l"(b));
    return r;
}
__device__ __forceinline__ u64 sub2(u64 a, u64 b) {
    u64 r;
    asm("sub.rn.f32x2 %0, %1, %2;" : "=l"(r) : "l"(a), "l"(b));
    return r;
}
// pack f32x2 (as u64) -> f16x2 (rounded)
__device__ __forceinline__ unsigned int pk_h2(u64 v) {
    unsigned int h;
    asm("{\n\t.reg .f32 lo, hi;\n\tmov.b64 {lo, hi}, %1;\n\t"
        "cvt.rn.f16x2.f32 %0, hi, lo;\n\t}"
        : "=r"(h) : "l"(v));
    return h;
}
// unpack f16x2 -> f32x2 (as u64)
__device__ __forceinline__ u64 upk_h2(unsigned int h) {
    u64 r;
    asm("{\n\t.reg .f16 a, b;\n\t.reg .f32 lo, hi;\n\t"
        "mov.b32 {a, b}, %1;\n\tcvt.f32.f16 lo, a;\n\tcvt.f32.f16 hi, b;\n\t"
        "mov.b64 %0, {lo, hi};\n\t}"
        : "=l"(r) : "r"(h));
    return r;
}

// ---- cp.async ----
__device__ __forceinline__ void cp16(float* dst, const float* src) {
    unsigned int s = (unsigned int)__cvta_generic_to_shared(dst);
    asm volatile("cp.async.cg.shared.global [%0], [%1], 16;\n" ::"r"(s),
                 "l"(src));
}
__device__ __forceinline__ void cp4(float* dst, const float* src) {
    unsigned int s = (unsigned int)__cvta_generic_to_shared(dst);
    asm volatile("cp.async.ca.shared.global [%0], [%1], 4;\n" ::"r"(s),
                 "l"(src));
}
__device__ __forceinline__ void cp_commit() {
    asm volatile("cp.async.commit_group;\n");
}
template <int N>
__device__ __forceinline__ void cp_wait() {
    asm volatile("cp.async.wait_group %0;\n" ::"n"(N));
}

__device__ __forceinline__ void stage_row(float* __restrict__ dst,
                                          const float* __restrict__ x, int row,
                                          int cb, int tid, bool edge) {
    const float* rp = x + (size_t)clampi(row, 0, IH - 1) * IW;
    if (!edge) {
        if (tid < XBUF_F / 4) cp16(dst + 4 * tid, rp + cb - 8 + 4 * tid);
    } else {
#pragma unroll
        for (int rr = 0; rr < 3; ++rr) {
            int m = tid + rr * NTH;
            if (m < XBUF_F) cp4(dst + m, rp + clampi(cb - 8 + m, 0, IW - 1));
        }
    }
}

struct State {
    u64 rh3[4];
    u64 rh5[8];
    u64 T3, T5;
    u64 Ts[NSP];
    float acc[8][2];
    u64 mcur;
};

// One chunk of LEN steps starting at tb; tb - t0 is a multiple of 16, so all
// ring slots / acc indices are compile-time constants (phase = p).
template <int LEN>
__device__ __forceinline__ void do_chunk(
    int tb, int r0, int r1, int cb, int c0,
    const float* __restrict__ x, const float* __restrict__ mp,
    float* __restrict__ outp, unsigned int* __restrict__ ring,
    float* __restrict__ xbuf, int tid, bool edge, State& st) {
#pragma unroll
    for (int p = 0; p < LEN; ++p) {
        const int t = tb + p;

        if ((p & 3) == 0) {
            cp_wait<2>();     // rows t..t+3 staged (distance 12)
            __syncthreads();  // visible; slots (p+12..15)&15 consumed
#pragma unroll
            for (int i = 0; i < 4; ++i)
                stage_row(xbuf + ((p + 12 + i) & 15) * XBUF_F, x, t + 12 + i,
                          cb, tid, edge);
            cp_commit();
        }

        // Prefetch map for next step's output row (t-6).
        const int nr = t - 6;
        u64 mnext = 0ull;
        if (nr >= r0 && nr < r1)
            mnext = *reinterpret_cast<const u64*>(mp + (size_t)nr * IW + c0);

        // Row t window: 9 aligned float2 loads (floats c0-8 .. c0+9).
        float2 xv[9];
        {
            const float2* xb2 = reinterpret_cast<const float2*>(
                xbuf + p * XBUF_F + 2 * tid);
#pragma unroll
            for (int i = 0; i < 9; ++i) xv[i] = xb2[i];
        }

        // Horizontal box sums, packed per column pair.
        const u64 pc = bc2(xv[4]);
        const u64 pL1 = pk2(xv[3].y, xv[4].x);
        const u64 pR1 = pk2(xv[4].y, xv[5].x);
        const u64 pL3 = pk2(xv[2].y, xv[3].x);
        const u64 pR3 = pk2(xv[5].y, xv[6].x);
        const u64 pL5 = pk2(xv[1].y, xv[2].x);
        const u64 pR5 = pk2(xv[6].y, xv[7].x);
        const u64 pL7 = pk2(xv[0].y, xv[1].x);
        const u64 pR7 = pk2(xv[7].y, xv[8].x);

        u64 h[7];
        h[0] = add2(add2(pc, pL1), pR1);
        h[1] = add2(add2(h[0], bc2(xv[3])), bc2(xv[5]));
        h[2] = add2(add2(h[1], pL3), pR3);
        h[3] = add2(add2(h[2], bc2(xv[2])), bc2(xv[6]));
        h[4] = add2(add2(h[3], pL5), pR5);
        h[5] = add2(add2(h[4], bc2(xv[1])), bc2(xv[7]));
        h[6] = add2(add2(h[5], pL7), pR7);

        // k=3: fp32x2 register ring (exact).
        {
            const u64 old = st.rh3[(p + 1) & 3];  // (p-3)&3
            st.rh3[p & 3] = h[0];
            st.T3 = add2(st.T3, sub2(h[0], old));
            const float2 tf = un2(st.T3);
            const int a = (p - 1) & 7;
            st.acc[a][0] = fmaf(WGT[0], tf.x, st.acc[a][0]);
            st.acc[a][1] = fmaf(WGT[0], tf.y, st.acc[a][1]);
        }
        // k=5: fp32x2 register ring (exact).
        {
            const u64 old = st.rh5[(p + 3) & 7];  // (p-5)&7
            st.rh5[p & 7] = h[1];
            st.T5 = add2(st.T5, sub2(h[1], old));
            const float2 tf = un2(st.T5);
            const int a = (p - 2) & 7;
            st.acc[a][0] = fmaf(WGT[1], tf.x, st.acc[a][0]);
            st.acc[a][1] = fmaf(WGT[1], tf.y, st.acc[a][1]);
        }

        // k=7..15: fp16 smem rings, drift-accepting.
#pragma unroll
        for (int j = 0; j < NSP; ++j) {
            const int r = j + 2;
            const int k = 2 * r + 3;
            const int d = SDEP[j];
            const int sw = p & (d - 1);
            const int sr = (p - k + 16) & (d - 1);

            const unsigned int oldh = ring[(SOFF[j] + sr) * NTH + tid];
            ring[(SOFF[j] + sw) * NTH + tid] = pk_h2(h[r]);

            st.Ts[j] = add2(st.Ts[j], sub2(h[r], upk_h2(oldh)));
            const float2 tf = un2(st.Ts[j]);
            const int a = (p - (r + 1)) & 7;
            st.acc[a][0] = fmaf(WGT[r], tf.x, st.acc[a][0]);
            st.acc[a][1] = fmaf(WGT[r], tf.y, st.acc[a][1]);
        }

        // Row t-7 complete: multiply by map (prefetched last step), store.
        const int orow = t - 7;
        const int fa = (p + 1) & 7;  // == (p - 7) & 7
        if (orow >= r0 && orow < r1) {
            const float2 mf = un2(st.mcur);
            float2 ov;
            ov.x = st.acc[fa][0] * mf.x;
            ov.y = st.acc[fa][1] * mf.y;
            *reinterpret_cast<float2*>(outp + (size_t)orow * IW + c0) = ov;
        }
        st.acc[fa][0] = 0.0f;
        st.acc[fa][1] = 0.0f;
        st.mcur = mnext;
    }
}

}  // namespace

__global__ void __launch_bounds__(NTH, 4)
MeanConv_82008105549850_kernel(const float* __restrict__ x,
                               const float* __restrict__ mp,
                               float* __restrict__ outp) {
    extern __shared__ __align__(16) char smem_raw[];
    unsigned int* ring = reinterpret_cast<unsigned int*>(smem_raw);  // f16x2
    float* xbuf = reinterpret_cast<float*>(smem_raw + RING_BYTES);

    const int tid = threadIdx.x;
    const int cb = blockIdx.x * TW;
    const bool edge = (cb == 0) || (cb + TW == IW);
    const int r0 = blockIdx.y * SROWS;
    const int r1 = min(r0 + SROWS, IH);
    const int c0 = cb + 2 * tid;

    const int t0 = r0 - 7;  // 7 warm-up rows; 125 steps = 7*16 + 13

    // Prologue: stage rows t0..t0+11 as 3 groups of 4 into slots 0..11.
#pragma unroll
    for (int g = 0; g < 3; ++g) {
#pragma unroll
        for (int i = 0; i < 4; ++i)
            stage_row(xbuf + (4 * g + i) * XBUF_F, x, t0 + 4 * g + i, cb, tid,
                      edge);
        cp_commit();
    }

    // Zero this thread's ring column (open-window warm-up). Private -> no sync.
#pragma unroll
    for (int s = 0; s < RINGROWS; ++s) ring[s * NTH + tid] = 0u;

    State st;
#pragma unroll
    for (int i = 0; i < 4; ++i) st.rh3[i] = 0ull;
#pragma unroll
    for (int i = 0; i < 8; ++i) st.rh5[i] = 0ull;
    st.T3 = st.T5 = 0ull;
#pragma unroll
    for (int j = 0; j < NSP; ++j) st.Ts[j] = 0ull;
#pragma unroll
    for (int a = 0; a < 8; ++a) st.acc[a][0] = st.acc[a][1] = 0.0f;
    st.mcur = 0ull;

    for (int chunk = 0; chunk < 7; ++chunk) {
        do_chunk<16>(t0 + chunk * 16, r0, r1, cb, c0, x, mp, outp, ring, xbuf,
                     tid, edge, st);
    }
    do_chunk<13>(t0 + 112, r0, r1, cb, c0, x, mp, outp, ring, xbuf, tid, edge,
                 st);
}

extern "C" void kernel_launch(void* const* d_in, const int* in_sizes, int n_in,
                              void* d_out, int out_size) {
    const float* x = (const float*)d_in[0];
    const float* mp = (const float*)d_in[1];
    float* outp = (float*)d_out;

    cudaFuncSetAttribute(MeanConv_82008105549850_kernel,
                         cudaFuncAttributeMaxDynamicSharedMemorySize,
                         SMEM_BYTES);

    dim3 grid(IW / TW, SEGS);  // 16 x 37 = 592 blocks = exactly 4/SM wave
    MeanConv_82008105549850_kernel<<<grid, NTH, SMEM_BYTES>>>(x, mp, outp);
}